// round 3
// baseline (speedup 1.0000x reference)
#include <cuda_runtime.h>
#include <math.h>

#define BATCH 8
#define LQ    2048
#define SK    2048
#define DIM   128
#define BM    128
#define BN    64
#define NTHREADS 256

// padded strides for shared tiles
#define QS_STRIDE (BM + 4)   // 132
#define KS_STRIDE (BN + 4)   // 68
#define PS_STRIDE (BM + 4)   // 132

// scratch for normalized Q (pre-scaled by 64) and normalized K
__device__ float g_qn[BATCH * LQ * DIM];
__device__ float g_kn[BATCH * SK * DIM];

// One block (32 threads) per row: L2-normalize, fold 64x temperature into Q.
__global__ void normalize_kernel(const float* __restrict__ q,
                                 const float* __restrict__ k) {
    int row = blockIdx.x;            // 0 .. BATCH*LQ + BATCH*SK - 1
    int lane = threadIdx.x;          // 0..31
    bool isQ = row < BATCH * LQ;
    int r = isQ ? row : row - BATCH * LQ;
    const float* src = (isQ ? q : k) + (size_t)r * DIM;
    float*       dst = (isQ ? g_qn : g_kn) + (size_t)r * DIM;

    float4 v = ((const float4*)src)[lane];
    float ss = v.x * v.x + v.y * v.y + v.z * v.z + v.w * v.w;
#pragma unroll
    for (int off = 16; off > 0; off >>= 1)
        ss += __shfl_xor_sync(0xffffffffu, ss, off);
    float nrm = sqrtf(ss);
    float inv = (isQ ? 64.0f : 1.0f) / fmaxf(nrm, 1e-12f);
    v.x *= inv; v.y *= inv; v.z *= inv; v.w *= inv;
    ((float4*)dst)[lane] = v;
}

// Flash attention, fp32 CUDA-core baseline.
// CTA: BM=128 query rows. Threads 256 = 16(ty) x 16(tx).
// QK stage: thread tile 8(rows) x 4(cols) over BMxBN scores.
// PV stage: thread tile 8(rows) x 8(cols) over BMxDIM output.
__global__ __launch_bounds__(NTHREADS, 1)
void attn_kernel(const float* __restrict__ value, float* __restrict__ out) {
    extern __shared__ float smem[];
    float* Qs = smem;                              // [DIM][QS_STRIDE] (transposed)
    float* Ks = Qs + DIM * QS_STRIDE;              // [DIM][KS_STRIDE] (transposed)
    float* Vs = Ks + DIM * KS_STRIDE;              // [BN][DIM]
    float* Ps = Vs + BN * DIM;                     // [BN][PS_STRIDE] (transposed P)

    const int b  = blockIdx.y;
    const int m0 = blockIdx.x * BM;
    const int tid = threadIdx.x;
    const int ty = tid >> 4;
    const int tx = tid & 15;

    // ---- load Q tile transposed into smem ----
    const float* qbase = g_qn + ((size_t)b * LQ + m0) * DIM;
#pragma unroll
    for (int it = 0; it < (BM * DIM / 4) / NTHREADS; it++) {
        int i = tid + it * NTHREADS;               // float4 index
        int row = i >> 5;                          // /32 float4 per row
        int d4  = i & 31;
        float4 v = ((const float4*)qbase)[i];
        Qs[(4 * d4 + 0) * QS_STRIDE + row] = v.x;
        Qs[(4 * d4 + 1) * QS_STRIDE + row] = v.y;
        Qs[(4 * d4 + 2) * QS_STRIDE + row] = v.z;
        Qs[(4 * d4 + 3) * QS_STRIDE + row] = v.w;
    }

    float o[8][8];
    float mprev[8], lsum[8];
#pragma unroll
    for (int i = 0; i < 8; i++) {
        mprev[i] = -INFINITY;
        lsum[i] = 0.0f;
#pragma unroll
        for (int j = 0; j < 8; j++) o[i][j] = 0.0f;
    }

    for (int s0 = 0; s0 < SK; s0 += BN) {
        __syncthreads();   // previous PV done before overwriting K/V
        const float* kbase = g_kn + ((size_t)b * SK + s0) * DIM;
        const float* vbase = value + ((size_t)b * SK + s0) * DIM;
#pragma unroll
        for (int it = 0; it < (BN * DIM / 4) / NTHREADS; it++) {
            int i = tid + it * NTHREADS;
            int row = i >> 5;
            int d4  = i & 31;
            float4 kv = ((const float4*)kbase)[i];
            Ks[(4 * d4 + 0) * KS_STRIDE + row] = kv.x;
            Ks[(4 * d4 + 1) * KS_STRIDE + row] = kv.y;
            Ks[(4 * d4 + 2) * KS_STRIDE + row] = kv.z;
            Ks[(4 * d4 + 3) * KS_STRIDE + row] = kv.w;
            float4 vv = ((const float4*)vbase)[i];
            ((float4*)(Vs + row * DIM))[d4] = vv;
        }
        __syncthreads();

        // ---- QK^T : scores (scale 64 already folded into Qn) ----
        float sc[8][4];
#pragma unroll
        for (int i = 0; i < 8; i++)
#pragma unroll
            for (int j = 0; j < 4; j++) sc[i][j] = 0.0f;

#pragma unroll 4
        for (int d = 0; d < DIM; d++) {
            float4 q0 = *(const float4*)(Qs + d * QS_STRIDE + ty * 8);
            float4 q1 = *(const float4*)(Qs + d * QS_STRIDE + ty * 8 + 4);
            float4 kf = *(const float4*)(Ks + d * KS_STRIDE + tx * 4);
            float qv[8] = {q0.x, q0.y, q0.z, q0.w, q1.x, q1.y, q1.z, q1.w};
            float kv[4] = {kf.x, kf.y, kf.z, kf.w};
#pragma unroll
            for (int i = 0; i < 8; i++)
#pragma unroll
                for (int j = 0; j < 4; j++)
                    sc[i][j] = fmaf(qv[i], kv[j], sc[i][j]);
        }

        // ---- online softmax (row stats allreduced over the 16 tx lanes) ----
#pragma unroll
        for (int i = 0; i < 8; i++) {
            float rmax = fmaxf(fmaxf(sc[i][0], sc[i][1]), fmaxf(sc[i][2], sc[i][3]));
#pragma unroll
            for (int off = 8; off > 0; off >>= 1)
                rmax = fmaxf(rmax, __shfl_xor_sync(0xffffffffu, rmax, off));
            float mnew = fmaxf(mprev[i], rmax);
            float corr = __expf(mprev[i] - mnew);
            float rs = 0.0f;
#pragma unroll
            for (int j = 0; j < 4; j++) {
                float p = __expf(sc[i][j] - mnew);
                sc[i][j] = p;
                rs += p;
            }
#pragma unroll
            for (int off = 8; off > 0; off >>= 1)
                rs += __shfl_xor_sync(0xffffffffu, rs, off);
            lsum[i] = lsum[i] * corr + rs;
            mprev[i] = mnew;
#pragma unroll
            for (int j = 0; j < 8; j++) o[i][j] *= corr;
            // write P transposed: Ps[n][m]
#pragma unroll
            for (int j = 0; j < 4; j++)
                Ps[(tx * 4 + j) * PS_STRIDE + ty * 8 + i] = sc[i][j];
        }
        __syncthreads();

        // ---- O += P * V ----
#pragma unroll 2
        for (int kk = 0; kk < BN; kk++) {
            float4 p0 = *(const float4*)(Ps + kk * PS_STRIDE + ty * 8);
            float4 p1 = *(const float4*)(Ps + kk * PS_STRIDE + ty * 8 + 4);
            float4 v0 = *(const float4*)(Vs + kk * DIM + tx * 8);
            float4 v1 = *(const float4*)(Vs + kk * DIM + tx * 8 + 4);
            float pv[8] = {p0.x, p0.y, p0.z, p0.w, p1.x, p1.y, p1.z, p1.w};
            float vv[8] = {v0.x, v0.y, v0.z, v0.w, v1.x, v1.y, v1.z, v1.w};
#pragma unroll
            for (int i = 0; i < 8; i++)
#pragma unroll
                for (int j = 0; j < 8; j++)
                    o[i][j] = fmaf(pv[i], vv[j], o[i][j]);
        }
    }

    // ---- epilogue: divide by row sums, write out ----
    float* obase = out + ((size_t)b * LQ + m0) * DIM;
#pragma unroll
    for (int i = 0; i < 8; i++) {
        float inv = 1.0f / lsum[i];
        int row = ty * 8 + i;
        float4 r0 = make_float4(o[i][0] * inv, o[i][1] * inv, o[i][2] * inv, o[i][3] * inv);
        float4 r1 = make_float4(o[i][4] * inv, o[i][5] * inv, o[i][6] * inv, o[i][7] * inv);
        *(float4*)(obase + (size_t)row * DIM + tx * 8)     = r0;
        *(float4*)(obase + (size_t)row * DIM + tx * 8 + 4) = r1;
    }
}

extern "C" void kernel_launch(void* const* d_in, const int* in_sizes, int n_in,
                              void* d_out, int out_size) {
    const float* q = (const float*)d_in[0];
    const float* k = (const float*)d_in[1];
    const float* v = (const float*)d_in[2];
    float* out = (float*)d_out;

    normalize_kernel<<<BATCH * LQ + BATCH * SK, 32>>>(q, k);

    size_t smem_bytes = (size_t)(DIM * QS_STRIDE + DIM * KS_STRIDE +
                                 BN * DIM + BN * PS_STRIDE) * sizeof(float);
    cudaFuncSetAttribute(attn_kernel,
                         cudaFuncAttributeMaxDynamicSharedMemorySize,
                         (int)smem_bytes);
    dim3 grid(LQ / BM, BATCH);
    attn_kernel<<<grid, NTHREADS, smem_bytes>>>(v, out);
}

// round 4
// speedup vs baseline: 1.8823x; 1.8823x over previous
#include <cuda_runtime.h>
#include <math.h>

#define BATCH 8
#define LQ    2048
#define SK    2048
#define DIM   128
#define BM    128
#define BN    64
#define NTHREADS 256

#define QSTR 132   // floats per Q/K/V smem row (DIM + 4 pad)
#define PSTR 68    // floats per P smem row (BN + 4 pad)

// scratch for normalized Q (pre-scaled by 64) and normalized K
__device__ float g_qn[BATCH * LQ * DIM];
__device__ float g_kn[BATCH * SK * DIM];

// 256 threads, 8 rows per block (one warp per row).
__global__ void normalize_kernel(const float* __restrict__ q,
                                 const float* __restrict__ k) {
    int row = blockIdx.x * 8 + (threadIdx.x >> 5);
    int lane = threadIdx.x & 31;
    bool isQ = row < BATCH * LQ;
    int r = isQ ? row : row - BATCH * LQ;
    const float* src = (isQ ? q : k) + (size_t)r * DIM;
    float*       dst = (isQ ? g_qn : g_kn) + (size_t)r * DIM;

    float4 v = ((const float4*)src)[lane];
    float ss = v.x * v.x + v.y * v.y + v.z * v.z + v.w * v.w;
#pragma unroll
    for (int off = 16; off > 0; off >>= 1)
        ss += __shfl_xor_sync(0xffffffffu, ss, off);
    float inv = (isQ ? 64.0f : 1.0f) / fmaxf(sqrtf(ss), 1e-12f);
    v.x *= inv; v.y *= inv; v.z *= inv; v.w *= inv;
    ((float4*)dst)[lane] = v;
}

// Flash attention fp32, conflict-free shared layout.
// 256 threads = 16(ty) x 16(tx).
// QK: thread tile 8 rows (ty*8+i) x 4 cols (j*16+tx).
// PV: thread tile 8 rows x 8 cols (tx*4+j  and  64+tx*4+j).
__global__ __launch_bounds__(NTHREADS, 1)
void attn_kernel(const float* __restrict__ value, float* __restrict__ out) {
    extern __shared__ float smem[];
    float* Qs = smem;                       // [BM][QSTR], d4 xor-swizzled per row
    float* Ks = Qs + BM * QSTR;             // [BN][QSTR], row-major
    float* Vs = Ks + BN * QSTR;             // [BN][QSTR], row-major
    float* Ps = Vs + BN * QSTR;             // [BM][PSTR], n-quad xor-swizzled per row

    const int b   = blockIdx.y;
    const int m0  = blockIdx.x * BM;
    const int tid = threadIdx.x;
    const int ty  = tid >> 4;
    const int tx  = tid & 15;

    // ---- load Q tile row-major, swizzle d4 by (row>>3)&7 ----
    const float* qbase = g_qn + ((size_t)b * LQ + m0) * DIM;
#pragma unroll
    for (int it = 0; it < (BM * DIM / 4) / NTHREADS; it++) {
        int i = tid + it * NTHREADS;
        int row = i >> 5;
        int d4  = i & 31;
        int sw  = d4 ^ ((row >> 3) & 7);
        *(float4*)(Qs + row * QSTR + 4 * sw) = ((const float4*)qbase)[i];
    }

    float o[8][8];
    float mprev[8], lsum[8];
#pragma unroll
    for (int i = 0; i < 8; i++) {
        mprev[i] = -INFINITY;
        lsum[i] = 0.0f;
#pragma unroll
        for (int j = 0; j < 8; j++) o[i][j] = 0.0f;
    }

    const int qsw = ty & 7;      // swizzle sel for this thread's Q/P rows
    const float* kbase = g_kn + (size_t)b * SK * DIM;
    const float* vbase = value + (size_t)b * SK * DIM;

    for (int s0 = 0; s0 < SK; s0 += BN) {
        __syncthreads();   // prev PV done before overwriting K/V
#pragma unroll
        for (int it = 0; it < (BN * DIM / 4) / NTHREADS; it++) {
            int i = tid + it * NTHREADS;
            int row = i >> 5;
            int d4  = i & 31;
            *(float4*)(Ks + row * QSTR + 4 * d4) =
                ((const float4*)(kbase + (size_t)s0 * DIM))[i];
            *(float4*)(Vs + row * QSTR + 4 * d4) =
                ((const float4*)(vbase + (size_t)s0 * DIM))[i];
        }
        __syncthreads();

        // ---- QK^T ----
        float sc[8][4];
#pragma unroll
        for (int i = 0; i < 8; i++)
#pragma unroll
            for (int j = 0; j < 4; j++) sc[i][j] = 0.0f;

#pragma unroll 2
        for (int d4 = 0; d4 < DIM / 4; d4++) {
            float4 kr[4];
#pragma unroll
            for (int j = 0; j < 4; j++)
                kr[j] = *(const float4*)(Ks + (j * 16 + tx) * QSTR + 4 * d4);
#pragma unroll
            for (int i = 0; i < 8; i++) {
                float4 qr = *(const float4*)(Qs + (ty * 8 + i) * QSTR +
                                             4 * (d4 ^ qsw));
#pragma unroll
                for (int j = 0; j < 4; j++) {
                    sc[i][j] = fmaf(qr.x, kr[j].x, sc[i][j]);
                    sc[i][j] = fmaf(qr.y, kr[j].y, sc[i][j]);
                    sc[i][j] = fmaf(qr.z, kr[j].z, sc[i][j]);
                    sc[i][j] = fmaf(qr.w, kr[j].w, sc[i][j]);
                }
            }
        }

        // ---- online softmax; P stored row-major with quad swizzle ----
#pragma unroll
        for (int i = 0; i < 8; i++) {
            float rmax = fmaxf(fmaxf(sc[i][0], sc[i][1]), fmaxf(sc[i][2], sc[i][3]));
#pragma unroll
            for (int off = 8; off > 0; off >>= 1)
                rmax = fmaxf(rmax, __shfl_xor_sync(0xffffffffu, rmax, off));
            float mnew = fmaxf(mprev[i], rmax);
            float rs = 0.0f;
#pragma unroll
            for (int j = 0; j < 4; j++) {
                float p = __expf(sc[i][j] - mnew);
                sc[i][j] = p;
                rs += p;
            }
#pragma unroll
            for (int off = 8; off > 0; off >>= 1)
                rs += __shfl_xor_sync(0xffffffffu, rs, off);
            if (mnew > mprev[i]) {
                float corr = __expf(mprev[i] - mnew);
                lsum[i] = lsum[i] * corr + rs;
                mprev[i] = mnew;
#pragma unroll
                for (int j = 0; j < 8; j++) o[i][j] *= corr;
            } else {
                lsum[i] += rs;
            }
            // store P[m][n], n = j*16+tx, quad-swizzled by row
            float* prow = Ps + (ty * 8 + i) * PSTR;
#pragma unroll
            for (int j = 0; j < 4; j++) {
                int n = j * 16 + tx;
                prow[4 * ((n >> 2) ^ qsw) + (n & 3)] = sc[i][j];
            }
        }
        __syncthreads();

        // ---- O += P * V ----
#pragma unroll 1
        for (int k4 = 0; k4 < BN / 4; k4++) {
            float4 pr[8];
#pragma unroll
            for (int i = 0; i < 8; i++)
                pr[i] = *(const float4*)(Ps + (ty * 8 + i) * PSTR +
                                         4 * (k4 ^ qsw));
#pragma unroll
            for (int kk = 0; kk < 4; kk++) {
                float4 v0 = *(const float4*)(Vs + (k4 * 4 + kk) * QSTR + tx * 4);
                float4 v1 = *(const float4*)(Vs + (k4 * 4 + kk) * QSTR + 64 + tx * 4);
#pragma unroll
                for (int i = 0; i < 8; i++) {
                    float p = (kk == 0) ? pr[i].x : (kk == 1) ? pr[i].y
                             : (kk == 2) ? pr[i].z : pr[i].w;
                    o[i][0] = fmaf(p, v0.x, o[i][0]);
                    o[i][1] = fmaf(p, v0.y, o[i][1]);
                    o[i][2] = fmaf(p, v0.z, o[i][2]);
                    o[i][3] = fmaf(p, v0.w, o[i][3]);
                    o[i][4] = fmaf(p, v1.x, o[i][4]);
                    o[i][5] = fmaf(p, v1.y, o[i][5]);
                    o[i][6] = fmaf(p, v1.z, o[i][6]);
                    o[i][7] = fmaf(p, v1.w, o[i][7]);
                }
            }
        }
    }

    // ---- epilogue ----
    float* obase = out + ((size_t)b * LQ + m0) * DIM;
#pragma unroll
    for (int i = 0; i < 8; i++) {
        float inv = 1.0f / lsum[i];
        size_t roff = (size_t)(ty * 8 + i) * DIM;
        *(float4*)(obase + roff + tx * 4) =
            make_float4(o[i][0] * inv, o[i][1] * inv, o[i][2] * inv, o[i][3] * inv);
        *(float4*)(obase + roff + 64 + tx * 4) =
            make_float4(o[i][4] * inv, o[i][5] * inv, o[i][6] * inv, o[i][7] * inv);
    }
}

extern "C" void kernel_launch(void* const* d_in, const int* in_sizes, int n_in,
                              void* d_out, int out_size) {
    const float* q = (const float*)d_in[0];
    const float* k = (const float*)d_in[1];
    const float* v = (const float*)d_in[2];
    float* out = (float*)d_out;

    normalize_kernel<<<(BATCH * (LQ + SK)) / 8, 256>>>(q, k);

    size_t smem_bytes = (size_t)(BM * QSTR + 2 * BN * QSTR + BM * PSTR) * sizeof(float);
    cudaFuncSetAttribute(attn_kernel,
                         cudaFuncAttributeMaxDynamicSharedMemorySize,
                         (int)smem_bytes);
    dim3 grid(LQ / BM, BATCH);
    attn_kernel<<<grid, NTHREADS, smem_bytes>>>(v, out);
}

// round 5
// speedup vs baseline: 5.1501x; 2.7361x over previous
#include <cuda_runtime.h>
#include <cuda_bf16.h>
#include <math.h>
#include <stdint.h>

#define BATCH 8
#define LQ    2048
#define SK    2048
#define DIM   128
#define BM    128
#define BN    64
#define NTHREADS 256
#define QSTRB 136            // bf16 per smem row (DIM + 8 pad) -> 272B row stride

// scratch for normalized Q (pre-scaled by 64) and normalized K (fp32)
__device__ float g_qn[BATCH * LQ * DIM];
__device__ float g_kn[BATCH * SK * DIM];

__global__ void normalize_kernel(const float* __restrict__ q,
                                 const float* __restrict__ k) {
    int row = blockIdx.x * 8 + (threadIdx.x >> 5);
    int lane = threadIdx.x & 31;
    bool isQ = row < BATCH * LQ;
    int r = isQ ? row : row - BATCH * LQ;
    const float* src = (isQ ? q : k) + (size_t)r * DIM;
    float*       dst = (isQ ? g_qn : g_kn) + (size_t)r * DIM;

    float4 v = ((const float4*)src)[lane];
    float ss = v.x * v.x + v.y * v.y + v.z * v.z + v.w * v.w;
#pragma unroll
    for (int off = 16; off > 0; off >>= 1)
        ss += __shfl_xor_sync(0xffffffffu, ss, off);
    float inv = (isQ ? 64.0f : 1.0f) / fmaxf(sqrtf(ss), 1e-12f);
    v.x *= inv; v.y *= inv; v.z *= inv; v.w *= inv;
    ((float4*)dst)[lane] = v;
}

__device__ __forceinline__ uint32_t smem_u32(const void* p) {
    return (uint32_t)__cvta_generic_to_shared(p);
}
__device__ __forceinline__ void ldsm_x4(uint32_t& r0, uint32_t& r1,
                                        uint32_t& r2, uint32_t& r3, uint32_t a) {
    asm volatile("ldmatrix.sync.aligned.m8n8.x4.shared.b16 {%0,%1,%2,%3}, [%4];"
                 : "=r"(r0), "=r"(r1), "=r"(r2), "=r"(r3) : "r"(a));
}
__device__ __forceinline__ void ldsm_x4t(uint32_t& r0, uint32_t& r1,
                                         uint32_t& r2, uint32_t& r3, uint32_t a) {
    asm volatile("ldmatrix.sync.aligned.m8n8.x4.trans.shared.b16 {%0,%1,%2,%3}, [%4];"
                 : "=r"(r0), "=r"(r1), "=r"(r2), "=r"(r3) : "r"(a));
}
__device__ __forceinline__ void mma16816(float* c, uint32_t a0, uint32_t a1,
                                         uint32_t a2, uint32_t a3,
                                         uint32_t b0, uint32_t b1) {
    asm volatile(
        "mma.sync.aligned.m16n8k16.row.col.f32.bf16.bf16.f32 "
        "{%0,%1,%2,%3}, {%4,%5,%6,%7}, {%8,%9}, {%0,%1,%2,%3};"
        : "+f"(c[0]), "+f"(c[1]), "+f"(c[2]), "+f"(c[3])
        : "r"(a0), "r"(a1), "r"(a2), "r"(a3), "r"(b0), "r"(b1));
}
__device__ __forceinline__ uint32_t pack_bf16(float a, float b) {
    __nv_bfloat162 t;
    t.x = __float2bfloat16_rn(a);
    t.y = __float2bfloat16_rn(b);
    return *(uint32_t*)&t;
}
// split x into hi (returned packed pair) writing residuals
__device__ __forceinline__ void split2(float x, float y, uint32_t& hi, uint32_t& lo) {
    __nv_bfloat16 hx = __float2bfloat16_rn(x);
    __nv_bfloat16 hy = __float2bfloat16_rn(y);
    float rx = x - __bfloat162float(hx);
    float ry = y - __bfloat162float(hy);
    __nv_bfloat162 h; h.x = hx; h.y = hy;
    hi = *(uint32_t*)&h;
    lo = pack_bf16(rx, ry);
}

__global__ __launch_bounds__(NTHREADS, 1)
void attn_kernel(const float* __restrict__ value, float* __restrict__ out) {
    extern __shared__ __nv_bfloat16 smem[];
    __nv_bfloat16* Qh = smem;                    // [BM][QSTRB]
    __nv_bfloat16* Ql = Qh + BM * QSTRB;
    __nv_bfloat16* Kh = Ql + BM * QSTRB;         // [BN][QSTRB]
    __nv_bfloat16* Kl = Kh + BN * QSTRB;
    __nv_bfloat16* Vh = Kl + BN * QSTRB;         // [BN][QSTRB]
    __nv_bfloat16* Vl = Vh + BN * QSTRB;

    const int b    = blockIdx.y;
    const int m0   = blockIdx.x * BM;
    const int tid  = threadIdx.x;
    const int warp = tid >> 5;
    const int lane = tid & 31;
    const int g    = lane >> 2;      // group id (row within 8)
    const int t4   = lane & 3;

    // ---- load + split Q tile ----
    const float* qbase = g_qn + ((size_t)b * LQ + m0) * DIM;
#pragma unroll
    for (int it = 0; it < (BM * DIM / 4) / NTHREADS; it++) {
        int i = tid + it * NTHREADS;
        int row = i >> 5;
        int d4  = i & 31;
        float4 v = ((const float4*)qbase)[i];
        uint32_t h0, l0, h1, l1;
        split2(v.x, v.y, h0, l0);
        split2(v.z, v.w, h1, l1);
        uint32_t off = row * QSTRB + 4 * d4;
        *(uint32_t*)(Qh + off)     = h0;
        *(uint32_t*)(Qh + off + 2) = h1;
        *(uint32_t*)(Ql + off)     = l0;
        *(uint32_t*)(Ql + off + 2) = l1;
    }

    float o[16][4];
    float sc[8][4];
    float m0_ = -INFINITY, m1_ = -INFINITY, l0_ = 0.0f, l1_ = 0.0f;
#pragma unroll
    for (int j = 0; j < 16; j++)
#pragma unroll
        for (int c = 0; c < 4; c++) o[j][c] = 0.0f;

    // precomputed per-thread ldmatrix offsets (bytes)
    const uint32_t qh0 = smem_u32(Qh), ql0 = smem_u32(Ql);
    const uint32_t kh0 = smem_u32(Kh), kl0 = smem_u32(Kl);
    const uint32_t vh0 = smem_u32(Vh), vl0 = smem_u32(Vl);
    const uint32_t qoff = (uint32_t)(16 * warp + (lane & 15)) * (QSTRB * 2) +
                          (uint32_t)(lane >> 4) * 16;
    const uint32_t koff = (uint32_t)((lane >> 4) * 8 + (lane & 7)) * (QSTRB * 2) +
                          (uint32_t)(lane & 8) * 2;
    const uint32_t voff = (uint32_t)((lane & 8) + (lane & 7)) * (QSTRB * 2) +
                          (uint32_t)((lane & 16) >> 1) * 2;

    const float* kbase = g_kn + (size_t)b * SK * DIM;
    const float* vbase = value + (size_t)b * SK * DIM;

    for (int s0 = 0; s0 < SK; s0 += BN) {
        __syncthreads();
#pragma unroll
        for (int it = 0; it < (BN * DIM / 4) / NTHREADS; it++) {
            int i = tid + it * NTHREADS;
            int row = i >> 5;
            int d4  = i & 31;
            uint32_t off = row * QSTRB + 4 * d4;
            float4 kv = ((const float4*)(kbase + (size_t)s0 * DIM))[i];
            uint32_t h0, l0r, h1, l1r;
            split2(kv.x, kv.y, h0, l0r);
            split2(kv.z, kv.w, h1, l1r);
            *(uint32_t*)(Kh + off)     = h0;
            *(uint32_t*)(Kh + off + 2) = h1;
            *(uint32_t*)(Kl + off)     = l0r;
            *(uint32_t*)(Kl + off + 2) = l1r;
            float4 vv = ((const float4*)(vbase + (size_t)s0 * DIM))[i];
            split2(vv.x, vv.y, h0, l0r);
            split2(vv.z, vv.w, h1, l1r);
            *(uint32_t*)(Vh + off)     = h0;
            *(uint32_t*)(Vh + off + 2) = h1;
            *(uint32_t*)(Vl + off)     = l0r;
            *(uint32_t*)(Vl + off + 2) = l1r;
        }
        __syncthreads();

        // ---- S = Qn Kn^T (3-pass hi/lo) ----
#pragma unroll
        for (int j = 0; j < 8; j++)
#pragma unroll
            for (int c = 0; c < 4; c++) sc[j][c] = 0.0f;

#pragma unroll
        for (int ks = 0; ks < DIM / 16; ks++) {
            uint32_t dbyte = (uint32_t)(ks * 16) * 2;
            uint32_t ah0, ah1, ah2, ah3, al0, al1, al2, al3;
            ldsm_x4(ah0, ah1, ah2, ah3, qh0 + qoff + dbyte);
            ldsm_x4(al0, al1, al2, al3, ql0 + qoff + dbyte);
#pragma unroll
            for (int jp = 0; jp < 4; jp++) {
                uint32_t nbyte = (uint32_t)(16 * jp) * (QSTRB * 2);
                uint32_t bh0, bh1, bh2, bh3, bl0, bl1, bl2, bl3;
                ldsm_x4(bh0, bh1, bh2, bh3, kh0 + koff + nbyte + dbyte);
                ldsm_x4(bl0, bl1, bl2, bl3, kl0 + koff + nbyte + dbyte);
                mma16816(sc[2 * jp],     ah0, ah1, ah2, ah3, bh0, bh1);
                mma16816(sc[2 * jp],     ah0, ah1, ah2, ah3, bl0, bl1);
                mma16816(sc[2 * jp],     al0, al1, al2, al3, bh0, bh1);
                mma16816(sc[2 * jp + 1], ah0, ah1, ah2, ah3, bh2, bh3);
                mma16816(sc[2 * jp + 1], ah0, ah1, ah2, ah3, bl2, bl3);
                mma16816(sc[2 * jp + 1], al0, al1, al2, al3, bh2, bh3);
            }
        }

        // ---- online softmax (rows g and g+8 of this warp's 16) ----
        float rmax0 = -INFINITY, rmax1 = -INFINITY;
#pragma unroll
        for (int j = 0; j < 8; j++) {
            rmax0 = fmaxf(rmax0, fmaxf(sc[j][0], sc[j][1]));
            rmax1 = fmaxf(rmax1, fmaxf(sc[j][2], sc[j][3]));
        }
#pragma unroll
        for (int off = 1; off <= 2; off <<= 1) {
            rmax0 = fmaxf(rmax0, __shfl_xor_sync(0xffffffffu, rmax0, off));
            rmax1 = fmaxf(rmax1, __shfl_xor_sync(0xffffffffu, rmax1, off));
        }
        float mnew0 = fmaxf(m0_, rmax0);
        float mnew1 = fmaxf(m1_, rmax1);
        float rs0 = 0.0f, rs1 = 0.0f;
#pragma unroll
        for (int j = 0; j < 8; j++) {
            sc[j][0] = __expf(sc[j][0] - mnew0);
            sc[j][1] = __expf(sc[j][1] - mnew0);
            sc[j][2] = __expf(sc[j][2] - mnew1);
            sc[j][3] = __expf(sc[j][3] - mnew1);
            rs0 += sc[j][0] + sc[j][1];
            rs1 += sc[j][2] + sc[j][3];
        }
#pragma unroll
        for (int off = 1; off <= 2; off <<= 1) {
            rs0 += __shfl_xor_sync(0xffffffffu, rs0, off);
            rs1 += __shfl_xor_sync(0xffffffffu, rs1, off);
        }
        if (mnew0 > m0_) {
            float corr = __expf(m0_ - mnew0);
            l0_ = l0_ * corr + rs0;
            m0_ = mnew0;
#pragma unroll
            for (int j = 0; j < 16; j++) { o[j][0] *= corr; o[j][1] *= corr; }
        } else l0_ += rs0;
        if (mnew1 > m1_) {
            float corr = __expf(m1_ - mnew1);
            l1_ = l1_ * corr + rs1;
            m1_ = mnew1;
#pragma unroll
            for (int j = 0; j < 16; j++) { o[j][2] *= corr; o[j][3] *= corr; }
        } else l1_ += rs1;

        // ---- build P fragments (hi/lo) in registers ----
        uint32_t ph[4][4], pl[4][4];
#pragma unroll
        for (int kk = 0; kk < 4; kk++) {
            int j0 = 2 * kk, j1 = 2 * kk + 1;
            split2(sc[j0][0], sc[j0][1], ph[kk][0], pl[kk][0]);
            split2(sc[j0][2], sc[j0][3], ph[kk][1], pl[kk][1]);
            split2(sc[j1][0], sc[j1][1], ph[kk][2], pl[kk][2]);
            split2(sc[j1][2], sc[j1][3], ph[kk][3], pl[kk][3]);
        }

        // ---- O += P V (3-pass hi/lo) ----
#pragma unroll
        for (int dp = 0; dp < 8; dp++) {
            uint32_t dbyte = (uint32_t)(16 * dp) * 2;
#pragma unroll
            for (int kk = 0; kk < 4; kk++) {
                uint32_t sbyte = (uint32_t)(16 * kk) * (QSTRB * 2);
                uint32_t bh0, bh1, bh2, bh3, bl0, bl1, bl2, bl3;
                ldsm_x4t(bh0, bh1, bh2, bh3, vh0 + voff + sbyte + dbyte);
                ldsm_x4t(bl0, bl1, bl2, bl3, vl0 + voff + sbyte + dbyte);
                mma16816(o[2 * dp], ph[kk][0], ph[kk][1], ph[kk][2], ph[kk][3], bh0, bh1);
                mma16816(o[2 * dp], ph[kk][0], ph[kk][1], ph[kk][2], ph[kk][3], bl0, bl1);
                mma16816(o[2 * dp], pl[kk][0], pl[kk][1], pl[kk][2], pl[kk][3], bh0, bh1);
                mma16816(o[2 * dp + 1], ph[kk][0], ph[kk][1], ph[kk][2], ph[kk][3], bh2, bh3);
                mma16816(o[2 * dp + 1], ph[kk][0], ph[kk][1], ph[kk][2], ph[kk][3], bl2, bl3);
                mma16816(o[2 * dp + 1], pl[kk][0], pl[kk][1], pl[kk][2], pl[kk][3], bh2, bh3);
            }
        }
    }

    // ---- epilogue ----
    float inv0 = 1.0f / l0_;
    float inv1 = 1.0f / l1_;
    int r0 = m0 + 16 * warp + g;
    float* ob0 = out + ((size_t)b * LQ + r0) * DIM;
    float* ob1 = ob0 + 8 * DIM;
#pragma unroll
    for (int j = 0; j < 16; j++) {
        int c = 8 * j + 2 * t4;
        ob0[c]     = o[j][0] * inv0;
        ob0[c + 1] = o[j][1] * inv0;
        ob1[c]     = o[j][2] * inv1;
        ob1[c + 1] = o[j][3] * inv1;
    }
}

extern "C" void kernel_launch(void* const* d_in, const int* in_sizes, int n_in,
                              void* d_out, int out_size) {
    const float* q = (const float*)d_in[0];
    const float* k = (const float*)d_in[1];
    const float* v = (const float*)d_in[2];
    float* out = (float*)d_out;

    normalize_kernel<<<(BATCH * (LQ + SK)) / 8, 256>>>(q, k);

    size_t smem_bytes = (size_t)(2 * BM * QSTRB + 4 * BN * QSTRB) * sizeof(__nv_bfloat16);
    cudaFuncSetAttribute(attn_kernel,
                         cudaFuncAttributeMaxDynamicSharedMemorySize,
                         (int)smem_bytes);
    dim3 grid(LQ / BM, BATCH);
    attn_kernel<<<grid, NTHREADS, smem_bytes>>>(v, out);
}